// round 1
// baseline (speedup 1.0000x reference)
#include <cuda_runtime.h>
#include <cuda_bf16.h>

// ---------------------------------------------------------------------------
// GaussianVoxelizer: binned gather
//   H=160, W=160, D=16 voxels, voxel 0.4, vol_min (-32,-32,-1)
//   8192 gaussians, 32 features, SCALE_MULTIPLIER = 3
// Pipeline (all launches on default stream, graph-capturable, no allocs):
//   1. zero tile counts
//   2. per-gaussian preprocess (cov_inv, 3sigma bounds, tile range, count)
//   3. prefix scan over 800 tiles
//   4. fill per-tile gaussian lists
//   5. per-tile gather: 512 threads = 8x8x8 voxels, register accumulators
// ---------------------------------------------------------------------------

#define NG      8192
#define HN      160
#define WN      160
#define DN      16
#define VSZ     0.4f
#define VMX     (-32.0f)
#define VMY     (-32.0f)
#define VMZ     (-1.0f)

#define TSH     3              // tile shift (8 voxels per tile per dim)
#define TXN     (HN >> TSH)    // 20
#define TYN     (WN >> TSH)    // 20
#define TZN     (DN >> TSH)    // 2
#define NTILES  (TXN * TYN * TZN)   // 800

#define LIST_CAP (NG * 24)     // hard math bound is NG*18; margin
#define CCHUNK   128           // gaussians staged in smem per chunk

// ---- static scratch (no allocs allowed) ----
__device__ float    g_params[NG * 16];    // per-gaussian packed params
__device__ unsigned g_range[NG];          // packed tile range (0xFFFFFFFF = empty)
__device__ int      g_counts[NTILES];
__device__ int      g_offsets[NTILES + 1];
__device__ int      g_cursor[NTILES];
__device__ int      g_list[LIST_CAP];

// ---------------------------------------------------------------------------
__global__ void k_zero() {
    int t = blockIdx.x * blockDim.x + threadIdx.x;
    if (t < NTILES) g_counts[t] = 0;
}

// ---------------------------------------------------------------------------
__global__ void k_prep(const float* __restrict__ means,
                       const float* __restrict__ opac,
                       const float* __restrict__ scl,
                       const float* __restrict__ rot) {
    int g = blockIdx.x * blockDim.x + threadIdx.x;
    if (g >= NG) return;

    float qw = rot[4 * g + 0], qx = rot[4 * g + 1];
    float qy = rot[4 * g + 2], qz = rot[4 * g + 3];
    float qn = rsqrtf(qw * qw + qx * qx + qy * qy + qz * qz);
    qw *= qn; qx *= qn; qy *= qn; qz *= qn;

    float r00 = 1.f - 2.f * (qy * qy + qz * qz);
    float r01 = 2.f * (qx * qy - qw * qz);
    float r02 = 2.f * (qx * qz + qw * qy);
    float r10 = 2.f * (qx * qy + qw * qz);
    float r11 = 1.f - 2.f * (qx * qx + qz * qz);
    float r12 = 2.f * (qy * qz - qw * qx);
    float r20 = 2.f * (qx * qz - qw * qy);
    float r21 = 2.f * (qy * qz + qw * qx);
    float r22 = 1.f - 2.f * (qx * qx + qy * qy);

    float s0 = scl[3 * g + 0], s1 = scl[3 * g + 1], s2 = scl[3 * g + 2];
    float v0 = s0 * s0, v1 = s1 * s1, v2 = s2 * s2;
    float a0 = 1.f / v0, a1 = 1.f / v1, a2 = 1.f / v2;

    // cov_inv = R diag(1/s^2) R^T   (exact inverse of R S^2 R^T)
    float i00 = r00 * r00 * a0 + r01 * r01 * a1 + r02 * r02 * a2;
    float i01 = r00 * r10 * a0 + r01 * r11 * a1 + r02 * r12 * a2;
    float i02 = r00 * r20 * a0 + r01 * r21 * a1 + r02 * r22 * a2;
    float i11 = r10 * r10 * a0 + r11 * r11 * a1 + r12 * r12 * a2;
    float i12 = r10 * r20 * a0 + r11 * r21 * a1 + r12 * r22 * a2;
    float i22 = r20 * r20 * a0 + r21 * r21 * a1 + r22 * r22 * a2;

    // diag(cov) for sigma
    float c00 = r00 * r00 * v0 + r01 * r01 * v1 + r02 * r02 * v2;
    float c11 = r10 * r10 * v0 + r11 * r11 * v1 + r12 * r12 * v2;
    float c22 = r20 * r20 * v0 + r21 * r21 * v1 + r22 * r22 * v2;
    float bx = 3.f * sqrtf(c00);
    float by = 3.f * sqrtf(c11);
    float bz = 3.f * sqrtf(c22);

    float mx = means[3 * g + 0], my = means[3 * g + 1], mz = means[3 * g + 2];
    float op = opac[g];

    float* p = &g_params[g * 16];
    p[0] = mx;  p[1] = my;  p[2] = mz;  p[3] = op;
    p[4] = bx;  p[5] = by;  p[6] = bz;  p[7] = 0.f;
    p[8] = i00; p[9] = i01; p[10] = i02; p[11] = i11;
    p[12] = i12; p[13] = i22; p[14] = 0.f; p[15] = 0.f;

    // voxel index range per dim (center index space), conservative slack
    float mu[3] = { mx, my, mz };
    float bb[3] = { bx, by, bz };
    const float vmin[3] = { VMX, VMY, VMZ };
    const int nd[3] = { HN, WN, DN };
    int lo[3], hi[3];
    bool ok = true;
#pragma unroll
    for (int d = 0; d < 3; d++) {
        float l = (mu[d] - bb[d] - vmin[d]) / VSZ - 0.5f;
        float h = (mu[d] + bb[d] - vmin[d]) / VSZ - 0.5f;
        int i0 = (int)ceilf(l - 1e-3f);  if (i0 < 0) i0 = 0;
        int i1 = (int)floorf(h + 1e-3f); if (i1 > nd[d] - 1) i1 = nd[d] - 1;
        if (i0 > i1) ok = false;
        lo[d] = i0 >> TSH; hi[d] = i1 >> TSH;
    }
    if (!ok) { g_range[g] = 0xFFFFFFFFu; return; }

    g_range[g] = (unsigned)lo[0] | ((unsigned)hi[0] << 5)
               | ((unsigned)lo[1] << 10) | ((unsigned)hi[1] << 15)
               | ((unsigned)lo[2] << 20) | ((unsigned)hi[2] << 25);

    for (int tx = lo[0]; tx <= hi[0]; tx++)
        for (int ty = lo[1]; ty <= hi[1]; ty++)
            for (int tz = lo[2]; tz <= hi[2]; tz++)
                atomicAdd(&g_counts[(tx * TYN + ty) * TZN + tz], 1);
}

// ---------------------------------------------------------------------------
__global__ void k_scan() {
    __shared__ int buf[1024];
    int t = threadIdx.x;
    int v = (t < NTILES) ? g_counts[t] : 0;
    buf[t] = v;
    __syncthreads();
    for (int off = 1; off < 1024; off <<= 1) {
        int x = (t >= off) ? buf[t - off] : 0;
        __syncthreads();
        buf[t] += x;
        __syncthreads();
    }
    if (t < NTILES) {
        int excl = buf[t] - v;
        g_offsets[t] = excl;
        g_cursor[t]  = excl;
        if (t == NTILES - 1) g_offsets[NTILES] = buf[t];
    }
}

// ---------------------------------------------------------------------------
__global__ void k_fill() {
    int g = blockIdx.x * blockDim.x + threadIdx.x;
    if (g >= NG) return;
    unsigned r = g_range[g];
    if (r == 0xFFFFFFFFu) return;
    int x0 = r & 31, x1 = (r >> 5) & 31;
    int y0 = (r >> 10) & 31, y1 = (r >> 15) & 31;
    int z0 = (r >> 20) & 31, z1 = (r >> 25) & 31;
    for (int tx = x0; tx <= x1; tx++)
        for (int ty = y0; ty <= y1; ty++)
            for (int tz = z0; tz <= z1; tz++) {
                int tile = (tx * TYN + ty) * TZN + tz;
                int pos = atomicAdd(&g_cursor[tile], 1);
                if (pos < LIST_CAP) g_list[pos] = g;
            }
}

// ---------------------------------------------------------------------------
__global__ __launch_bounds__(512)
void k_main(const float* __restrict__ feat, float* __restrict__ out) {
    __shared__ int    s_idx[CCHUNK];
    __shared__ float4 s_par[CCHUNK * 4];   // mu.xyz,op | b.xyz,_ | i00..i11 | i12,i22,_,_
    __shared__ float4 s_fea[CCHUNK * 8];   // 32 features

    int bt = blockIdx.x;
    int tz = bt % TZN;
    int ty = (bt / TZN) % TYN;
    int tx = bt / (TZN * TYN);

    int tid = threadIdx.x;
    int lk = tid & 7;
    int lj = (tid >> 3) & 7;
    int li = tid >> 6;

    int vi = (tx << TSH) + li;
    int vj = (ty << TSH) + lj;
    int vk = (tz << TSH) + lk;

    float px = ((float)vi + 0.5f) * VSZ + VMX;
    float py = ((float)vj + 0.5f) * VSZ + VMY;
    float pz = ((float)vk + 0.5f) * VSZ + VMZ;

    float4 acc[8];
#pragma unroll
    for (int r = 0; r < 8; r++) acc[r] = make_float4(0.f, 0.f, 0.f, 0.f);

    int tile = (tx * TYN + ty) * TZN + tz;
    int start = g_offsets[tile];
    int n = g_offsets[tile + 1] - start;

    const float4* gp4 = (const float4*)g_params;
    const float4* gf4 = (const float4*)feat;

    for (int base = 0; base < n; base += CCHUNK) {
        int cnt = min(CCHUNK, n - base);
        __syncthreads();                 // protect previous-iteration reads
        if (tid < cnt) s_idx[tid] = g_list[start + base + tid];
        __syncthreads();
        for (int u = tid; u < cnt * 4; u += 512) {
            int c = u >> 2, pc = u & 3;
            s_par[u] = gp4[s_idx[c] * 4 + pc];
        }
        for (int u = tid; u < cnt * 8; u += 512) {
            int c = u >> 3, pc = u & 7;
            s_fea[u] = gf4[s_idx[c] * 8 + pc];
        }
        __syncthreads();

        for (int c = 0; c < cnt; c++) {
            float4 p0 = s_par[c * 4 + 0];
            float4 p1 = s_par[c * 4 + 1];
            float dx = px - p0.x, dy = py - p0.y, dz = pz - p0.z;
            if (fabsf(dx) <= p1.x && fabsf(dy) <= p1.y && fabsf(dz) <= p1.z) {
                float4 p2 = s_par[c * 4 + 2];
                float4 p3 = s_par[c * 4 + 3];
                float maha = p2.x * dx * dx + p2.w * dy * dy + p3.y * dz * dz
                           + 2.f * (p2.y * dx * dy + p2.z * dx * dz + p3.x * dy * dz);
                float w = p0.w * __expf(-0.5f * maha);
                const float4* f = &s_fea[c * 8];
#pragma unroll
                for (int r = 0; r < 8; r++) {
                    float4 fv = f[r];
                    acc[r].x += w * fv.x;
                    acc[r].y += w * fv.y;
                    acc[r].z += w * fv.z;
                    acc[r].w += w * fv.w;
                }
            }
        }
    }

    // one coalesced write per voxel: out[(vi*W + vj)*D + vk][0..31]
    long long v = ((long long)vi * WN + vj) * DN + vk;
    float4* o4 = (float4*)(out + v * 32);
#pragma unroll
    for (int r = 0; r < 8; r++) o4[r] = acc[r];
}

// ---------------------------------------------------------------------------
extern "C" void kernel_launch(void* const* d_in, const int* in_sizes, int n_in,
                              void* d_out, int out_size) {
    const float* means = (const float*)d_in[0];   // 8192 x 3
    const float* opac  = (const float*)d_in[1];   // 8192 x 1
    const float* scl   = (const float*)d_in[2];   // 8192 x 3
    const float* rot   = (const float*)d_in[3];   // 8192 x 4
    const float* feat  = (const float*)d_in[4];   // 8192 x 32
    float* out = (float*)d_out;                   // 160*160*16*32

    k_zero<<<(NTILES + 255) / 256, 256>>>();
    k_prep<<<(NG + 255) / 256, 256>>>(means, opac, scl, rot);
    k_scan<<<1, 1024>>>();
    k_fill<<<(NG + 255) / 256, 256>>>();
    k_main<<<NTILES, 512>>>(feat, out);
}

// round 2
// speedup vs baseline: 1.3579x; 1.3579x over previous
#include <cuda_runtime.h>
#include <cuda_bf16.h>

// ---------------------------------------------------------------------------
// GaussianVoxelizer: binned gather, round 2
//   3 launches: prep (+zero counts) -> bin (pair-parallel atomics) -> main
//   Fixed-capacity per-tile lists kill the count/scan/fill serial-atomic chain.
//   k_main: 256 thr/block, 2 voxels per thread (z and z+4), shared xy mask.
// ---------------------------------------------------------------------------

#define NG      8192
#define HN      160
#define WN      160
#define DN      16
#define VSZ     0.4f
#define VMX     (-32.0f)
#define VMY     (-32.0f)
#define VMZ     (-1.0f)

#define TSH     3              // 8 voxels per tile per dim
#define TXN     (HN >> TSH)    // 20
#define TYN     (WN >> TSH)    // 20
#define TZN     (DN >> TSH)    // 2
#define NTILES  (TXN * TYN * TZN)   // 800

#define TCAP    256            // per-tile list capacity (expected ~62, max span 18/gauss)
#define CCHUNK  128            // gaussians staged in smem per chunk

// ---- static scratch ----
__device__ float    g_params[NG * 16];
__device__ unsigned g_range[NG];
__device__ int      g_cnt[NTILES];
__device__ int      g_list[NTILES * TCAP];

// ---------------------------------------------------------------------------
__global__ void k_prep(const float* __restrict__ means,
                       const float* __restrict__ opac,
                       const float* __restrict__ scl,
                       const float* __restrict__ rot) {
    int g = blockIdx.x * blockDim.x + threadIdx.x;
    if (g < NTILES) g_cnt[g] = 0;          // fold count-zeroing into prep
    if (g >= NG) return;

    float qw = rot[4 * g + 0], qx = rot[4 * g + 1];
    float qy = rot[4 * g + 2], qz = rot[4 * g + 3];
    float qn = rsqrtf(qw * qw + qx * qx + qy * qy + qz * qz);
    qw *= qn; qx *= qn; qy *= qn; qz *= qn;

    float r00 = 1.f - 2.f * (qy * qy + qz * qz);
    float r01 = 2.f * (qx * qy - qw * qz);
    float r02 = 2.f * (qx * qz + qw * qy);
    float r10 = 2.f * (qx * qy + qw * qz);
    float r11 = 1.f - 2.f * (qx * qx + qz * qz);
    float r12 = 2.f * (qy * qz - qw * qx);
    float r20 = 2.f * (qx * qz - qw * qy);
    float r21 = 2.f * (qy * qz + qw * qx);
    float r22 = 1.f - 2.f * (qx * qx + qy * qy);

    float s0 = scl[3 * g + 0], s1 = scl[3 * g + 1], s2 = scl[3 * g + 2];
    float v0 = s0 * s0, v1 = s1 * s1, v2 = s2 * s2;
    float a0 = 1.f / v0, a1 = 1.f / v1, a2 = 1.f / v2;

    // cov_inv = R diag(1/s^2) R^T (exact analytic inverse)
    float i00 = r00 * r00 * a0 + r01 * r01 * a1 + r02 * r02 * a2;
    float i01 = r00 * r10 * a0 + r01 * r11 * a1 + r02 * r12 * a2;
    float i02 = r00 * r20 * a0 + r01 * r21 * a1 + r02 * r22 * a2;
    float i11 = r10 * r10 * a0 + r11 * r11 * a1 + r12 * r12 * a2;
    float i12 = r10 * r20 * a0 + r11 * r21 * a1 + r12 * r22 * a2;
    float i22 = r20 * r20 * a0 + r21 * r21 * a1 + r22 * r22 * a2;

    float c00 = r00 * r00 * v0 + r01 * r01 * v1 + r02 * r02 * v2;
    float c11 = r10 * r10 * v0 + r11 * r11 * v1 + r12 * r12 * v2;
    float c22 = r20 * r20 * v0 + r21 * r21 * v1 + r22 * r22 * v2;
    float bx = 3.f * sqrtf(c00);
    float by = 3.f * sqrtf(c11);
    float bz = 3.f * sqrtf(c22);

    float mx = means[3 * g + 0], my = means[3 * g + 1], mz = means[3 * g + 2];
    float op = opac[g];

    float* p = &g_params[g * 16];
    p[0] = mx;  p[1] = my;  p[2] = mz;  p[3] = op;
    p[4] = bx;  p[5] = by;  p[6] = bz;  p[7] = 0.f;
    p[8] = i00; p[9] = i01; p[10] = i02; p[11] = i11;
    p[12] = i12; p[13] = i22; p[14] = 0.f; p[15] = 0.f;

    float mu[3] = { mx, my, mz };
    float bb[3] = { bx, by, bz };
    const float vmin[3] = { VMX, VMY, VMZ };
    const int nd[3] = { HN, WN, DN };
    int lo[3], hi[3];
    bool ok = true;
#pragma unroll
    for (int d = 0; d < 3; d++) {
        float l = (mu[d] - bb[d] - vmin[d]) / VSZ - 0.5f;
        float h = (mu[d] + bb[d] - vmin[d]) / VSZ - 0.5f;
        int i0 = (int)ceilf(l - 1e-3f);  if (i0 < 0) i0 = 0;
        int i1 = (int)floorf(h + 1e-3f); if (i1 > nd[d] - 1) i1 = nd[d] - 1;
        if (i0 > i1) ok = false;
        lo[d] = i0 >> TSH; hi[d] = i1 >> TSH;
    }
    g_range[g] = ok ? ((unsigned)lo[0] | ((unsigned)hi[0] << 5)
                     | ((unsigned)lo[1] << 10) | ((unsigned)hi[1] << 15)
                     | ((unsigned)lo[2] << 20) | ((unsigned)hi[2] << 25))
                    : 0xFFFFFFFFu;
}

// ---------------------------------------------------------------------------
// one thread per (gaussian, slot): fully parallel independent atomics
__global__ void k_bin() {
    int t = blockIdx.x * blockDim.x + threadIdx.x;
    int g = t >> 5, slot = t & 31;
    if (g >= NG) return;
    unsigned r = g_range[g];
    if (r == 0xFFFFFFFFu) return;
    int x0 = r & 31, x1 = (r >> 5) & 31;
    int y0 = (r >> 10) & 31, y1 = (r >> 15) & 31;
    int z0 = (r >> 20) & 31, z1 = (r >> 25) & 31;
    int ny = y1 - y0 + 1, nz = z1 - z0 + 1;
    int nx = x1 - x0 + 1;
    if (slot >= nx * ny * nz) return;
    int sz = slot % nz; int rem = slot / nz;
    int sy = rem % ny;  int sx = rem / ny;
    int tile = ((x0 + sx) * TYN + (y0 + sy)) * TZN + (z0 + sz);
    int pos = atomicAdd(&g_cnt[tile], 1);
    if (pos < TCAP) g_list[tile * TCAP + pos] = g;
}

// ---------------------------------------------------------------------------
__global__ __launch_bounds__(256)
void k_main(const float* __restrict__ feat, float* __restrict__ out) {
    __shared__ int    s_idx[CCHUNK];
    __shared__ float4 s_par[CCHUNK * 4];
    __shared__ float4 s_fea[CCHUNK * 8];

    int bt = blockIdx.x;
    int tz = bt % TZN;
    int ty = (bt / TZN) % TYN;
    int tx = bt / (TZN * TYN);

    int tid = threadIdx.x;
    int lk = tid & 3;            // voxels lk and lk+4 in z
    int lj = (tid >> 2) & 7;
    int li = tid >> 5;

    int vi = (tx << TSH) + li;
    int vj = (ty << TSH) + lj;
    int vk = (tz << TSH) + lk;

    float px  = ((float)vi + 0.5f) * VSZ + VMX;
    float py  = ((float)vj + 0.5f) * VSZ + VMY;
    float pz0 = ((float)vk + 0.5f) * VSZ + VMZ;
    float pz1 = pz0 + 4.f * VSZ;

    float4 a0[8], a1[8];
#pragma unroll
    for (int r = 0; r < 8; r++) {
        a0[r] = make_float4(0.f, 0.f, 0.f, 0.f);
        a1[r] = make_float4(0.f, 0.f, 0.f, 0.f);
    }

    int tile = (tx * TYN + ty) * TZN + tz;
    int n = min(g_cnt[tile], TCAP);

    const float4* gp4 = (const float4*)g_params;
    const float4* gf4 = (const float4*)feat;

    for (int base = 0; base < n; base += CCHUNK) {
        int cnt = min(CCHUNK, n - base);
        __syncthreads();
        if (tid < cnt) s_idx[tid] = g_list[tile * TCAP + base + tid];
        __syncthreads();
        for (int u = tid; u < cnt * 4; u += 256) {
            int c = u >> 2, pc = u & 3;
            s_par[u] = gp4[s_idx[c] * 4 + pc];
        }
        for (int u = tid; u < cnt * 8; u += 256) {
            int c = u >> 3, pc = u & 7;
            s_fea[u] = gf4[s_idx[c] * 8 + pc];
        }
        __syncthreads();

        for (int c = 0; c < cnt; c++) {
            float4 p0 = s_par[c * 4 + 0];
            float4 p1 = s_par[c * 4 + 1];
            float dx = px - p0.x, dy = py - p0.y;
            float dz0 = pz0 - p0.z, dz1 = pz1 - p0.z;
            bool inxy = (fabsf(dx) <= p1.x) && (fabsf(dy) <= p1.y);
            bool in0 = inxy && (fabsf(dz0) <= p1.z);
            bool in1 = inxy && (fabsf(dz1) <= p1.z);
            if (in0 || in1) {
                float4 p2 = s_par[c * 4 + 2];
                float4 p3 = s_par[c * 4 + 3];
                float mb = p2.x * dx * dx + p2.w * dy * dy + 2.f * p2.y * dx * dy;
                float cz = 2.f * (p2.z * dx + p3.x * dy);
                float m0 = mb + dz0 * (p3.y * dz0 + cz);
                float m1 = mb + dz1 * (p3.y * dz1 + cz);
                float w0 = in0 ? p0.w * __expf(-0.5f * m0) : 0.f;
                float w1 = in1 ? p0.w * __expf(-0.5f * m1) : 0.f;
                const float4* f = &s_fea[c * 8];
#pragma unroll
                for (int r = 0; r < 8; r++) {
                    float4 fv = f[r];
                    a0[r].x += w0 * fv.x; a0[r].y += w0 * fv.y;
                    a0[r].z += w0 * fv.z; a0[r].w += w0 * fv.w;
                    a1[r].x += w1 * fv.x; a1[r].y += w1 * fv.y;
                    a1[r].z += w1 * fv.z; a1[r].w += w1 * fv.w;
                }
            }
        }
    }

    long long v0 = ((long long)vi * WN + vj) * DN + vk;
    float4* o0 = (float4*)(out + v0 * 32);
    float4* o1 = (float4*)(out + (v0 + 4) * 32);
#pragma unroll
    for (int r = 0; r < 8; r++) o0[r] = a0[r];
#pragma unroll
    for (int r = 0; r < 8; r++) o1[r] = a1[r];
}

// ---------------------------------------------------------------------------
extern "C" void kernel_launch(void* const* d_in, const int* in_sizes, int n_in,
                              void* d_out, int out_size) {
    const float* means = (const float*)d_in[0];
    const float* opac  = (const float*)d_in[1];
    const float* scl   = (const float*)d_in[2];
    const float* rot   = (const float*)d_in[3];
    const float* feat  = (const float*)d_in[4];
    float* out = (float*)d_out;

    k_prep<<<(NG + 255) / 256, 256>>>(means, opac, scl, rot);
    k_bin<<<(NG * 32 + 255) / 256, 256>>>();
    k_main<<<NTILES, 256>>>(feat, out);
}

// round 3
// speedup vs baseline: 1.4145x; 1.0416x over previous
#include <cuda_runtime.h>
#include <cuda_bf16.h>

// ---------------------------------------------------------------------------
// GaussianVoxelizer round 3: 2 launches
//   k_prepbin: warp per gaussian; lane0 computes cov_inv/bounds (no x32 MUFU
//              redundancy), shfl-broadcast range, lane-per-tile-slot atomics.
//   k_main:    block per 8x8x8 tile, 128 threads x 4 contiguous z-voxels,
//              exp2-folded cov_inv (1 MUFU per weight), resets tile counter.
// ---------------------------------------------------------------------------

#define NG      8192
#define HN      160
#define WN      160
#define DN      16
#define VSZ     0.4f
#define VMX     (-32.0f)
#define VMY     (-32.0f)
#define VMZ     (-1.0f)

#define TSH     3
#define TXN     (HN >> TSH)         // 20
#define TYN     (WN >> TSH)         // 20
#define TZN     (DN >> TSH)         // 2
#define NTILES  (TXN * TYN * TZN)   // 800

#define TCAP    256
#define CCHUNK  128
#define KEXP2   0.72134752044448170f   // 0.5 * log2(e)

__device__ float g_params[NG * 16];
__device__ int   g_cnt[NTILES];        // zero-init at load; k_main re-zeros
__device__ int   g_list[NTILES * TCAP];

__device__ __forceinline__ float ex2(float x) {
    float r;
    asm("ex2.approx.f32 %0, %1;" : "=f"(r) : "f"(x));
    return r;
}

// ---------------------------------------------------------------------------
__global__ void k_prepbin(const float* __restrict__ means,
                          const float* __restrict__ opac,
                          const float* __restrict__ scl,
                          const float* __restrict__ rot) {
    int t = blockIdx.x * blockDim.x + threadIdx.x;
    int g = t >> 5, lane = t & 31;
    if (g >= NG) return;

    unsigned range = 0xFFFFFFFFu;
    if (lane == 0) {
        float qw = rot[4 * g + 0], qx = rot[4 * g + 1];
        float qy = rot[4 * g + 2], qz = rot[4 * g + 3];
        float qn = rsqrtf(qw * qw + qx * qx + qy * qy + qz * qz);
        qw *= qn; qx *= qn; qy *= qn; qz *= qn;

        float r00 = 1.f - 2.f * (qy * qy + qz * qz);
        float r01 = 2.f * (qx * qy - qw * qz);
        float r02 = 2.f * (qx * qz + qw * qy);
        float r10 = 2.f * (qx * qy + qw * qz);
        float r11 = 1.f - 2.f * (qx * qx + qz * qz);
        float r12 = 2.f * (qy * qz - qw * qx);
        float r20 = 2.f * (qx * qz - qw * qy);
        float r21 = 2.f * (qy * qz + qw * qx);
        float r22 = 1.f - 2.f * (qx * qx + qy * qy);

        float s0 = scl[3 * g + 0], s1 = scl[3 * g + 1], s2 = scl[3 * g + 2];
        float v0 = s0 * s0, v1 = s1 * s1, v2 = s2 * s2;
        float a0 = 1.f / v0, a1 = 1.f / v1, a2 = 1.f / v2;

        // cov_inv = R diag(1/s^2) R^T, pre-scaled by 0.5*log2(e)
        float i00 = (r00 * r00 * a0 + r01 * r01 * a1 + r02 * r02 * a2) * KEXP2;
        float i01 = (r00 * r10 * a0 + r01 * r11 * a1 + r02 * r12 * a2) * KEXP2;
        float i02 = (r00 * r20 * a0 + r01 * r21 * a1 + r02 * r22 * a2) * KEXP2;
        float i11 = (r10 * r10 * a0 + r11 * r11 * a1 + r12 * r12 * a2) * KEXP2;
        float i12 = (r10 * r20 * a0 + r11 * r21 * a1 + r12 * r22 * a2) * KEXP2;
        float i22 = (r20 * r20 * a0 + r21 * r21 * a1 + r22 * r22 * a2) * KEXP2;

        float c00 = r00 * r00 * v0 + r01 * r01 * v1 + r02 * r02 * v2;
        float c11 = r10 * r10 * v0 + r11 * r11 * v1 + r12 * r12 * v2;
        float c22 = r20 * r20 * v0 + r21 * r21 * v1 + r22 * r22 * v2;
        float bx = 3.f * sqrtf(c00);
        float by = 3.f * sqrtf(c11);
        float bz = 3.f * sqrtf(c22);

        float mx = means[3 * g + 0], my = means[3 * g + 1], mz = means[3 * g + 2];
        float op = opac[g];

        float4* p4 = (float4*)&g_params[g * 16];
        p4[0] = make_float4(mx, my, mz, op);
        p4[1] = make_float4(bx, by, bz, 0.f);
        p4[2] = make_float4(i00, i01, i02, i11);
        p4[3] = make_float4(i12, i22, 0.f, 0.f);

        float mu[3] = { mx, my, mz };
        float bb[3] = { bx, by, bz };
        const float vmin[3] = { VMX, VMY, VMZ };
        const int nd[3] = { HN, WN, DN };
        int lo[3], hi[3];
        bool ok = true;
#pragma unroll
        for (int d = 0; d < 3; d++) {
            float l = (mu[d] - bb[d] - vmin[d]) / VSZ - 0.5f;
            float h = (mu[d] + bb[d] - vmin[d]) / VSZ - 0.5f;
            int i0 = (int)ceilf(l - 1e-3f);  if (i0 < 0) i0 = 0;
            int i1 = (int)floorf(h + 1e-3f); if (i1 > nd[d] - 1) i1 = nd[d] - 1;
            if (i0 > i1) ok = false;
            lo[d] = i0 >> TSH; hi[d] = i1 >> TSH;
        }
        if (ok)
            range = (unsigned)lo[0] | ((unsigned)hi[0] << 5)
                  | ((unsigned)lo[1] << 10) | ((unsigned)hi[1] << 15)
                  | ((unsigned)lo[2] << 20) | ((unsigned)hi[2] << 25);
    }
    range = __shfl_sync(0xffffffffu, range, 0);
    if (range == 0xFFFFFFFFu) return;

    int x0 = range & 31, x1 = (range >> 5) & 31;
    int y0 = (range >> 10) & 31, y1 = (range >> 15) & 31;
    int z0 = (range >> 20) & 31, z1 = (range >> 25) & 31;
    int nx = x1 - x0 + 1, ny = y1 - y0 + 1, nz = z1 - z0 + 1;
    if (lane >= nx * ny * nz) return;       // max span 3*3*2 = 18 <= 32
    int sz = lane % nz; int rem = lane / nz;
    int sy = rem % ny;  int sx = rem / ny;
    int tile = ((x0 + sx) * TYN + (y0 + sy)) * TZN + (z0 + sz);
    int pos = atomicAdd(&g_cnt[tile], 1);
    if (pos < TCAP) g_list[tile * TCAP + pos] = g;
}

// ---------------------------------------------------------------------------
__global__ __launch_bounds__(128)
void k_main(const float* __restrict__ feat, float* __restrict__ out) {
    __shared__ int    s_idx[CCHUNK];
    __shared__ float4 s_par[CCHUNK * 4];
    __shared__ float4 s_fea[CCHUNK * 8];

    int bt = blockIdx.x;
    int tz = bt % TZN;
    int ty = (bt / TZN) % TYN;
    int tx = bt / (TZN * TYN);

    int tid = threadIdx.x;
    int lk = (tid & 1) << 2;       // z base: 0 or 4, thread owns 4 contiguous z
    int lj = (tid >> 1) & 7;
    int li = tid >> 4;

    int vi = (tx << TSH) + li;
    int vj = (ty << TSH) + lj;
    int vk = (tz << TSH) + lk;

    float px  = ((float)vi + 0.5f) * VSZ + VMX;
    float py  = ((float)vj + 0.5f) * VSZ + VMY;
    float pz0 = ((float)vk + 0.5f) * VSZ + VMZ;
    float pzc = pz0 + 1.5f * VSZ;          // center of 4-voxel z span

    float4 acc[4][8];
#pragma unroll
    for (int z = 0; z < 4; z++)
#pragma unroll
        for (int r = 0; r < 8; r++) acc[z][r] = make_float4(0.f, 0.f, 0.f, 0.f);

    int tile = (tx * TYN + ty) * TZN + tz;
    int n = min(g_cnt[tile], TCAP);

    const float4* gp4 = (const float4*)g_params;
    const float4* gf4 = (const float4*)feat;

    for (int base = 0; base < n; base += CCHUNK) {
        int cnt = min(CCHUNK, n - base);
        __syncthreads();
        if (tid < cnt) s_idx[tid] = g_list[tile * TCAP + base + tid];
        __syncthreads();
        for (int u = tid; u < cnt * 4; u += 128) {
            int c = u >> 2, pc = u & 3;
            s_par[u] = gp4[s_idx[c] * 4 + pc];
        }
        for (int u = tid; u < cnt * 8; u += 128) {
            int c = u >> 3, pc = u & 7;
            s_fea[u] = gf4[s_idx[c] * 8 + pc];
        }
        __syncthreads();

        for (int c = 0; c < cnt; c++) {
            float4 p0 = s_par[c * 4 + 0];
            float4 p1 = s_par[c * 4 + 1];
            float dx = px - p0.x, dy = py - p0.y;
            float dzc = pzc - p0.z;
            if (fabsf(dx) <= p1.x && fabsf(dy) <= p1.y
                && fabsf(dzc) <= p1.z + 1.50001f * VSZ) {
                float4 p2 = s_par[c * 4 + 2];
                float4 p3 = s_par[c * 4 + 3];
                // scaled quadratic (already * 0.5*log2e)
                float mb = dx * (p2.x * dx + 2.f * p2.y * dy) + p2.w * dy * dy;
                float cz = 2.f * (p2.z * dx + p3.x * dy);
                float w[4];
#pragma unroll
                for (int z = 0; z < 4; z++) {
                    float dz = (pz0 + (float)z * VSZ) - p0.z;
                    float m  = mb + dz * (p3.y * dz + cz);
                    bool in  = fabsf(dz) <= p1.z;
                    w[z] = in ? p0.w * ex2(-m) : 0.f;
                }
                const float4* f = &s_fea[c * 8];
#pragma unroll
                for (int r = 0; r < 8; r++) {
                    float4 fv = f[r];
#pragma unroll
                    for (int z = 0; z < 4; z++) {
                        acc[z][r].x += w[z] * fv.x;
                        acc[z][r].y += w[z] * fv.y;
                        acc[z][r].z += w[z] * fv.z;
                        acc[z][r].w += w[z] * fv.w;
                    }
                }
            }
        }
    }

    long long v = ((long long)vi * WN + vj) * DN + vk;
    float* o = out + v * 32;
#pragma unroll
    for (int z = 0; z < 4; z++) {
        float4* o4 = (float4*)(o + z * 32);
#pragma unroll
        for (int r = 0; r < 8; r++) o4[r] = acc[z][r];
    }

    // reset this tile's counter so the next graph replay starts from zero
    __syncthreads();
    if (tid == 0) g_cnt[tile] = 0;
}

// ---------------------------------------------------------------------------
extern "C" void kernel_launch(void* const* d_in, const int* in_sizes, int n_in,
                              void* d_out, int out_size) {
    const float* means = (const float*)d_in[0];
    const float* opac  = (const float*)d_in[1];
    const float* scl   = (const float*)d_in[2];
    const float* rot   = (const float*)d_in[3];
    const float* feat  = (const float*)d_in[4];
    float* out = (float*)d_out;

    k_prepbin<<<(NG * 32 + 255) / 256, 256>>>(means, opac, scl, rot);
    k_main<<<NTILES, 128>>>(feat, out);
}